// round 2
// baseline (speedup 1.0000x reference)
#include <cuda_runtime.h>
#include <cstdint>

// Problem constants (fixed shapes from reference)
#define B_    16
#define N_    256
#define EDIM  1024
#define F_    2
#define C_    512          // EDIM / F_
#define NE    4096         // codebook size
#define NTOK  8192         // B_*F_*N_  (tokens total, also F_*NE proto rows)
#define BN    4096         // B_*N_ tokens per codebook
#define ZQ_ELEMS 4194304   // B_*N_*EDIM
#define EPS_  1e-12f

// ---- device scratch (no allocations allowed) ----
__device__ unsigned long long g_best[NTOK];   // packed (ord(d-min) , 0xFFFFFFFF-col)
__device__ float g_invp[NTOK];                // 1/max(||emb_row||,eps), full 8192-row table
__device__ float g_nrmz[NTOK];                // max(||zf_token||,eps)
__device__ float g_loss_part[NTOK];           // per-token loss partials

// float -> order-preserving uint32
__device__ __forceinline__ unsigned f2ord(float f) {
    unsigned u = __float_as_uint(f);
    return (u & 0x80000000u) ? ~u : (u | 0x80000000u);
}

// ---------------------------------------------------------------------------
// 0) init: clear argmin keys
// ---------------------------------------------------------------------------
__global__ void init_kernel() {
    int i = blockIdx.x * blockDim.x + threadIdx.x;
    if (i < NTOK) g_best[i] = 0ull;
}

// ---------------------------------------------------------------------------
// 1) norms: one warp per row. warps [0,8192): prototype rows; [8192,16384): tokens
// ---------------------------------------------------------------------------
__global__ void norms_kernel(const float* __restrict__ z, const float* __restrict__ emb) {
    int gw   = (blockIdx.x * blockDim.x + threadIdx.x) >> 5;
    int lane = threadIdx.x & 31;
    const float* p;
    if (gw < NTOK) {
        p = emb + (size_t)gw * C_;
    } else {
        int t  = gw - NTOK;
        int f  = t >> 12;
        int bn = t & (BN - 1);
        p = z + (size_t)bn * EDIM + f * C_;
    }
    float s = 0.f;
    #pragma unroll
    for (int q = 0; q < 4; q++) {
        float4 v = *reinterpret_cast<const float4*>(p + lane * 4 + q * 128);
        s += v.x * v.x + v.y * v.y + v.z * v.z + v.w * v.w;
    }
    #pragma unroll
    for (int o = 16; o > 0; o >>= 1) s += __shfl_xor_sync(0xFFFFFFFFu, s, o);
    if (lane == 0) {
        float nrm = fmaxf(sqrtf(s), EPS_);
        if (gw < NTOK) g_invp[gw] = 1.0f / nrm;
        else           g_nrmz[gw - NTOK] = nrm;
    }
}

// ---------------------------------------------------------------------------
// 2) fused GEMM + argmin:  s = (zf . p) * invp * invz ; d = 2 - 2s ; argmin over m
//    128x128 block tile, K-chunks of 32, 8x8 register tile, 256 threads.
// ---------------------------------------------------------------------------
#define TM 128
#define TN 128
#define KC 32
#define PAD 4

__global__ __launch_bounds__(256, 2)
void gemm_argmin_kernel(const float* __restrict__ z, const float* __restrict__ emb) {
    __shared__ float As[KC][TM + PAD];
    __shared__ float Bs[KC][TN + PAD];

    const int f  = blockIdx.z;
    const int m0 = blockIdx.y * TM;   // token tile (within codebook, 0..4095)
    const int n0 = blockIdx.x * TN;   // proto tile (within codebook)
    const int tid = threadIdx.x;
    const int tx = tid & 15;
    const int ty = tid >> 4;

    const float* Aptr = z   + (size_t)m0 * EDIM + f * C_;           // row stride EDIM
    const float* Bptr = emb + ((size_t)(f * NE + n0)) * C_;         // row stride C_

    float acc[8][8];
    #pragma unroll
    for (int i = 0; i < 8; i++)
        #pragma unroll
        for (int j = 0; j < 8; j++) acc[i][j] = 0.f;

    for (int k0 = 0; k0 < C_; k0 += KC) {
        #pragma unroll
        for (int i = 0; i < 4; i++) {
            int idx = tid + i * 256;
            int row = idx >> 3;
            int c4  = (idx & 7) * 4;
            float4 v = *reinterpret_cast<const float4*>(Aptr + (size_t)row * EDIM + k0 + c4);
            As[c4 + 0][row] = v.x; As[c4 + 1][row] = v.y;
            As[c4 + 2][row] = v.z; As[c4 + 3][row] = v.w;
        }
        #pragma unroll
        for (int i = 0; i < 4; i++) {
            int idx = tid + i * 256;
            int row = idx >> 3;
            int c4  = (idx & 7) * 4;
            float4 v = *reinterpret_cast<const float4*>(Bptr + (size_t)row * C_ + k0 + c4);
            Bs[c4 + 0][row] = v.x; Bs[c4 + 1][row] = v.y;
            Bs[c4 + 2][row] = v.z; Bs[c4 + 3][row] = v.w;
        }
        __syncthreads();
        #pragma unroll
        for (int k = 0; k < KC; k++) {
            float a[8], b[8];
            *reinterpret_cast<float4*>(&a[0]) = *reinterpret_cast<const float4*>(&As[k][ty * 8]);
            *reinterpret_cast<float4*>(&a[4]) = *reinterpret_cast<const float4*>(&As[k][ty * 8 + 4]);
            *reinterpret_cast<float4*>(&b[0]) = *reinterpret_cast<const float4*>(&Bs[k][tx * 8]);
            *reinterpret_cast<float4*>(&b[4]) = *reinterpret_cast<const float4*>(&Bs[k][tx * 8 + 4]);
            #pragma unroll
            for (int i = 0; i < 8; i++)
                #pragma unroll
                for (int j = 0; j < 8; j++) acc[i][j] += a[i] * b[j];
        }
        __syncthreads();
    }

    // epilogue: scale by prototype & token inverse norms, d = 2-2s, argmin with
    // first-index tie-break; reduce across the 16 tx lanes sharing a row group.
    float invp[8];
    #pragma unroll
    for (int j = 0; j < 8; j++) invp[j] = g_invp[f * NE + n0 + tx * 8 + j];

    #pragma unroll
    for (int i = 0; i < 8; i++) {
        int trow = f * BN + m0 + ty * 8 + i;          // token id
        float invz = 1.0f / g_nrmz[trow];
        unsigned long long key = 0ull;
        #pragma unroll
        for (int j = 0; j < 8; j++) {
            float s = acc[i][j] * invp[j] * invz;
            float d = __fsub_rn(2.0f, __fmul_rn(2.0f, s));   // match reference rounding
            unsigned ord = ~f2ord(d);                        // bigger = smaller d
            unsigned col = (unsigned)(n0 + tx * 8 + j);
            unsigned long long k2 = ((unsigned long long)ord << 32) | (0xFFFFFFFFu - col);
            if (k2 > key) key = k2;
        }
        #pragma unroll
        for (int o = 8; o >= 1; o >>= 1) {
            unsigned long long other = __shfl_xor_sync(0xFFFFFFFFu, key, o);
            if (other > key) key = other;
        }
        if ((tid & 15) == 0) atomicMax(&g_best[trow], key);
    }
}

// ---------------------------------------------------------------------------
// 3) gather + output + per-token loss partial. One block (128 thr) per token.
// ---------------------------------------------------------------------------
__global__ void gather_kernel(const float* __restrict__ z, const float* __restrict__ emb,
                              float* __restrict__ out, int out_size) {
    int t  = blockIdx.x;
    int f  = t >> 12;
    int bn = t & (BN - 1);
    int b  = bn >> 8;
    int n  = bn & 255;

    unsigned m = 0xFFFFFFFFu - (unsigned)(g_best[t] & 0xFFFFFFFFull);  // in [0, NE)
    float qscale = g_invp[m];       // gather from FULL table rows [0,4096) — matches reference
    float nz     = g_nrmz[t];

    int j = threadIdx.x * 4;
    float4 vq = *reinterpret_cast<const float4*>(emb + (size_t)m * C_ + j);
    float4 vz = *reinterpret_cast<const float4*>(z + (size_t)bn * EDIM + f * C_ + j);

    float o[4], lsum = 0.f;
    {
        float qv[4] = {vq.x, vq.y, vq.z, vq.w};
        float zv[4] = {vz.x, vz.y, vz.z, vz.w};
        #pragma unroll
        for (int q = 0; q < 4; q++) {
            float zq = __fmul_rn(qv[q], qscale);
            float zn = __fdiv_rn(zv[q], nz);
            float dd = __fsub_rn(zq, zn);
            o[q] = __fadd_rn(zn, dd);        // straight-through, exact reference rounding
            lsum += dd * dd;
        }
    }
    int obase = bn * EDIM + f * C_ + j;
    if (obase + 3 < out_size) {
        float4 ov; ov.x = o[0]; ov.y = o[1]; ov.z = o[2]; ov.w = o[3];
        *reinterpret_cast<float4*>(out + obase) = ov;
    }

    // deterministic block reduction of lsum (4 warps)
    #pragma unroll
    for (int ofs = 16; ofs > 0; ofs >>= 1) lsum += __shfl_xor_sync(0xFFFFFFFFu, lsum, ofs);
    __shared__ float sw[4];
    int lane = threadIdx.x & 31, wid = threadIdx.x >> 5;
    if (lane == 0) sw[wid] = lsum;
    __syncthreads();
    if (threadIdx.x == 0) {
        g_loss_part[t] = (sw[0] + sw[1]) + (sw[2] + sw[3]);
        int p = ZQ_ELEMS + 1 + ((b * 2 + f) << 8) + n;   // indices flat (b,f,n)
        if (p < out_size) out[p] = (float)m;
    }
}

// ---------------------------------------------------------------------------
// 4) final loss: deterministic fixed-order reduction of 8192 partials.
// ---------------------------------------------------------------------------
__global__ void loss_kernel(float* __restrict__ out, int out_size) {
    __shared__ float sh[256];
    float s = 0.f;
    for (int i = threadIdx.x; i < NTOK; i += 256) s += g_loss_part[i];
    sh[threadIdx.x] = s;
    __syncthreads();
    for (int st = 128; st > 0; st >>= 1) {
        if (threadIdx.x < st) sh[threadIdx.x] += sh[threadIdx.x + st];
        __syncthreads();
    }
    if (threadIdx.x == 0 && out_size > ZQ_ELEMS) {
        float mean = sh[0] / (float)ZQ_ELEMS;
        out[ZQ_ELEMS] = __fadd_rn(__fmul_rn(0.25f, mean), mean);  // BETA*mean + mean
    }
}

// ---------------------------------------------------------------------------
extern "C" void kernel_launch(void* const* d_in, const int* in_sizes, int n_in,
                              void* d_out, int out_size) {
    const float* z   = (const float*)d_in[0];
    const float* emb = (const float*)d_in[1];
    float* out = (float*)d_out;
    (void)in_sizes; (void)n_in;

    init_kernel<<<(NTOK + 255) / 256, 256>>>();
    norms_kernel<<<(2 * NTOK) / 8, 256>>>(z, emb);                 // 8 warps/block
    gemm_argmin_kernel<<<dim3(NE / TN, BN / TM, F_), 256>>>(z, emb);
    gather_kernel<<<NTOK, 128>>>(z, emb, out, out_size);
    loss_kernel<<<1, 256>>>(out, out_size);
}

// round 3
// speedup vs baseline: 1.0021x; 1.0021x over previous
#include <cuda_runtime.h>
#include <cstdint>

// Problem constants (fixed shapes from reference)
#define B_    16
#define N_    256
#define EDIM  1024
#define F_    2
#define C_    512          // EDIM / F_
#define NE    4096         // codebook size
#define NTOK  8192         // B_*F_*N_  (tokens total, also F_*NE proto rows)
#define BN    4096         // B_*N_ tokens per codebook
#define ZQ_ELEMS 4194304   // B_*N_*EDIM
#define EPS_  1e-12f

// ---- device scratch (no allocations allowed) ----
__device__ unsigned long long g_best[NTOK];   // packed (ord(d-min) , 0xFFFFFFFF-col)
__device__ float g_invp[NTOK];                // 1/max(||emb_row||,eps), full 8192-row table
__device__ float g_nrmz[NTOK];                // max(||zf_token||,eps)
__device__ float g_loss_part[NTOK];           // per-token loss partials

// float -> order-preserving uint32
__device__ __forceinline__ unsigned f2ord(float f) {
    unsigned u = __float_as_uint(f);
    return (u & 0x80000000u) ? ~u : (u | 0x80000000u);
}

// ---------------------------------------------------------------------------
// 0) init: clear argmin keys
// ---------------------------------------------------------------------------
__global__ void init_kernel() {
    int i = blockIdx.x * blockDim.x + threadIdx.x;
    if (i < NTOK) g_best[i] = 0ull;
}

// ---------------------------------------------------------------------------
// 1) norms: one warp per row. warps [0,8192): prototype rows; [8192,16384): tokens
// ---------------------------------------------------------------------------
__global__ void norms_kernel(const float* __restrict__ z, const float* __restrict__ emb) {
    int gw   = (blockIdx.x * blockDim.x + threadIdx.x) >> 5;
    int lane = threadIdx.x & 31;
    const float* p;
    if (gw < NTOK) {
        p = emb + (size_t)gw * C_;
    } else {
        int t  = gw - NTOK;
        int f  = t >> 12;
        int bn = t & (BN - 1);
        p = z + (size_t)bn * EDIM + f * C_;
    }
    float s = 0.f;
    #pragma unroll
    for (int q = 0; q < 4; q++) {
        float4 v = *reinterpret_cast<const float4*>(p + lane * 4 + q * 128);
        s += v.x * v.x + v.y * v.y + v.z * v.z + v.w * v.w;
    }
    #pragma unroll
    for (int o = 16; o > 0; o >>= 1) s += __shfl_xor_sync(0xFFFFFFFFu, s, o);
    if (lane == 0) {
        float nrm = fmaxf(sqrtf(s), EPS_);
        if (gw < NTOK) g_invp[gw] = 1.0f / nrm;
        else           g_nrmz[gw - NTOK] = nrm;
    }
}

// ---------------------------------------------------------------------------
// 2) fused GEMM + argmin:  s = (zf . p) * invp * invz ; d = 2 - 2s ; argmin over m
//    128x128 block tile, K-chunks of 32, 8x8 register tile, 256 threads.
// ---------------------------------------------------------------------------
#define TM 128
#define TN 128
#define KC 32
#define PAD 4

__global__ __launch_bounds__(256, 2)
void gemm_argmin_kernel(const float* __restrict__ z, const float* __restrict__ emb) {
    __shared__ float As[KC][TM + PAD];
    __shared__ float Bs[KC][TN + PAD];

    const int f  = blockIdx.z;
    const int m0 = blockIdx.y * TM;   // token tile (within codebook, 0..4095)
    const int n0 = blockIdx.x * TN;   // proto tile (within codebook)
    const int tid = threadIdx.x;
    const int tx = tid & 15;
    const int ty = tid >> 4;

    const float* Aptr = z   + (size_t)m0 * EDIM + f * C_;           // row stride EDIM
    const float* Bptr = emb + ((size_t)(f * NE + n0)) * C_;         // row stride C_

    float acc[8][8];
    #pragma unroll
    for (int i = 0; i < 8; i++)
        #pragma unroll
        for (int j = 0; j < 8; j++) acc[i][j] = 0.f;

    for (int k0 = 0; k0 < C_; k0 += KC) {
        #pragma unroll
        for (int i = 0; i < 4; i++) {
            int idx = tid + i * 256;
            int row = idx >> 3;
            int c4  = (idx & 7) * 4;
            float4 v = *reinterpret_cast<const float4*>(Aptr + (size_t)row * EDIM + k0 + c4);
            As[c4 + 0][row] = v.x; As[c4 + 1][row] = v.y;
            As[c4 + 2][row] = v.z; As[c4 + 3][row] = v.w;
        }
        #pragma unroll
        for (int i = 0; i < 4; i++) {
            int idx = tid + i * 256;
            int row = idx >> 3;
            int c4  = (idx & 7) * 4;
            float4 v = *reinterpret_cast<const float4*>(Bptr + (size_t)row * C_ + k0 + c4);
            Bs[c4 + 0][row] = v.x; Bs[c4 + 1][row] = v.y;
            Bs[c4 + 2][row] = v.z; Bs[c4 + 3][row] = v.w;
        }
        __syncthreads();
        #pragma unroll
        for (int k = 0; k < KC; k++) {
            float a[8], b[8];
            *reinterpret_cast<float4*>(&a[0]) = *reinterpret_cast<const float4*>(&As[k][ty * 8]);
            *reinterpret_cast<float4*>(&a[4]) = *reinterpret_cast<const float4*>(&As[k][ty * 8 + 4]);
            *reinterpret_cast<float4*>(&b[0]) = *reinterpret_cast<const float4*>(&Bs[k][tx * 8]);
            *reinterpret_cast<float4*>(&b[4]) = *reinterpret_cast<const float4*>(&Bs[k][tx * 8 + 4]);
            #pragma unroll
            for (int i = 0; i < 8; i++)
                #pragma unroll
                for (int j = 0; j < 8; j++) acc[i][j] += a[i] * b[j];
        }
        __syncthreads();
    }

    // epilogue: scale by prototype & token inverse norms, d = 2-2s, argmin with
    // first-index tie-break; reduce across the 16 tx lanes sharing a row group.
    float invp[8];
    #pragma unroll
    for (int j = 0; j < 8; j++) invp[j] = g_invp[f * NE + n0 + tx * 8 + j];

    #pragma unroll
    for (int i = 0; i < 8; i++) {
        int trow = f * BN + m0 + ty * 8 + i;          // token id
        float invz = 1.0f / g_nrmz[trow];
        unsigned long long key = 0ull;
        #pragma unroll
        for (int j = 0; j < 8; j++) {
            float s = acc[i][j] * invp[j] * invz;
            float d = __fsub_rn(2.0f, __fmul_rn(2.0f, s));   // match reference rounding
            unsigned ord = ~f2ord(d);                        // bigger = smaller d
            unsigned col = (unsigned)(n0 + tx * 8 + j);
            unsigned long long k2 = ((unsigned long long)ord << 32) | (0xFFFFFFFFu - col);
            if (k2 > key) key = k2;
        }
        #pragma unroll
        for (int o = 8; o >= 1; o >>= 1) {
            unsigned long long other = __shfl_xor_sync(0xFFFFFFFFu, key, o);
            if (other > key) key = other;
        }
        if ((tid & 15) == 0) atomicMax(&g_best[trow], key);
    }
}

// ---------------------------------------------------------------------------
// 3) gather + output + per-token loss partial. One block (128 thr) per token.
// ---------------------------------------------------------------------------
__global__ void gather_kernel(const float* __restrict__ z, const float* __restrict__ emb,
                              float* __restrict__ out, int out_size) {
    int t  = blockIdx.x;
    int f  = t >> 12;
    int bn = t & (BN - 1);
    int b  = bn >> 8;
    int n  = bn & 255;

    unsigned m = 0xFFFFFFFFu - (unsigned)(g_best[t] & 0xFFFFFFFFull);  // in [0, NE)
    float qscale = g_invp[m];       // gather from FULL table rows [0,4096) — matches reference
    float nz     = g_nrmz[t];

    int j = threadIdx.x * 4;
    float4 vq = *reinterpret_cast<const float4*>(emb + (size_t)m * C_ + j);
    float4 vz = *reinterpret_cast<const float4*>(z + (size_t)bn * EDIM + f * C_ + j);

    float o[4], lsum = 0.f;
    {
        float qv[4] = {vq.x, vq.y, vq.z, vq.w};
        float zv[4] = {vz.x, vz.y, vz.z, vz.w};
        #pragma unroll
        for (int q = 0; q < 4; q++) {
            float zq = __fmul_rn(qv[q], qscale);
            float zn = __fdiv_rn(zv[q], nz);
            float dd = __fsub_rn(zq, zn);
            o[q] = __fadd_rn(zn, dd);        // straight-through, exact reference rounding
            lsum += dd * dd;
        }
    }
    int obase = bn * EDIM + f * C_ + j;
    if (obase + 3 < out_size) {
        float4 ov; ov.x = o[0]; ov.y = o[1]; ov.z = o[2]; ov.w = o[3];
        *reinterpret_cast<float4*>(out + obase) = ov;
    }

    // deterministic block reduction of lsum (4 warps)
    #pragma unroll
    for (int ofs = 16; ofs > 0; ofs >>= 1) lsum += __shfl_xor_sync(0xFFFFFFFFu, lsum, ofs);
    __shared__ float sw[4];
    int lane = threadIdx.x & 31, wid = threadIdx.x >> 5;
    if (lane == 0) sw[wid] = lsum;
    __syncthreads();
    if (threadIdx.x == 0) {
        g_loss_part[t] = (sw[0] + sw[1]) + (sw[2] + sw[3]);
        int p = ZQ_ELEMS + 1 + ((b * 2 + f) << 8) + n;   // indices flat (b,f,n)
        if (p < out_size) out[p] = (float)m;
    }
}

// ---------------------------------------------------------------------------
// 4) final loss: deterministic fixed-order reduction of 8192 partials.
// ---------------------------------------------------------------------------
__global__ void loss_kernel(float* __restrict__ out, int out_size) {
    __shared__ float sh[256];
    float s = 0.f;
    for (int i = threadIdx.x; i < NTOK; i += 256) s += g_loss_part[i];
    sh[threadIdx.x] = s;
    __syncthreads();
    for (int st = 128; st > 0; st >>= 1) {
        if (threadIdx.x < st) sh[threadIdx.x] += sh[threadIdx.x + st];
        __syncthreads();
    }
    if (threadIdx.x == 0 && out_size > ZQ_ELEMS) {
        float mean = sh[0] / (float)ZQ_ELEMS;
        out[ZQ_ELEMS] = __fadd_rn(__fmul_rn(0.25f, mean), mean);  // BETA*mean + mean
    }
}

// ---------------------------------------------------------------------------
extern "C" void kernel_launch(void* const* d_in, const int* in_sizes, int n_in,
                              void* d_out, int out_size) {
    const float* z   = (const float*)d_in[0];
    const float* emb = (const float*)d_in[1];
    float* out = (float*)d_out;
    (void)in_sizes; (void)n_in;

    init_kernel<<<(NTOK + 255) / 256, 256>>>();
    norms_kernel<<<(2 * NTOK) / 8, 256>>>(z, emb);                 // 8 warps/block
    gemm_argmin_kernel<<<dim3(NE / TN, BN / TM, F_), 256>>>(z, emb);
    gather_kernel<<<NTOK, 128>>>(z, emb, out, out_size);
    loss_kernel<<<1, 256>>>(out, out_size);
}